// round 11
// baseline (speedup 1.0000x reference)
#include <cuda_runtime.h>
#include <cstdint>

// VectorQuantizer R7: codebook-in-REGISTERS, x-streamed-via-SMEM-broadcast.
// R3 was issue-bound on broadcast LDS (16 LDS.128 per thread per k). Now each
// warp owns 64 codebook rows in registers (2 full rows/thread); one x-row load
// (16 LDS.128) feeds 64 k's. Per-(point,k) arithmetic is bit-identical to R3
// (rel_err 0.0): same even/odd f32x2 accumulator split, (l0+h0)+(l1+h1),
// t = x_sq+e_sq, fmaf(-2,cross,t), exact first-index argmin via u64 lex-min.

#define C_DIM     64
#define K_EMB     512
#define HW        1024
#define NPTS      65536
#define NTHREADS  256
#define NCTAS     148
#define PPC       443                    // ceil(65536/148)
#define XSTRIDE   68                     // floats per staged x row (16B-mult, bank-skewed)

// SMEM layout (float offsets)
#define OFF_XSQ   (PPC * XSTRIDE)                        // 30124
#define OFF_PART  ((OFF_XSQ + PPC + 1) & ~1)             // 30568 (8B aligned)
#define PART_STR  9                                      // u64 stride per point (bank skew)
#define OFF_BESTK (OFF_PART + PPC * PART_STR * 2)        // 38542
#define SMEM_FLOATS (OFF_BESTK + PPC)                    // 38985
#define SMEM_BYTES  (SMEM_FLOATS * 4)                    // 155940 (< 228KB)
// codebook re-stage occupies floats [0, 512*68) = byte 139264 < OFF_BESTK*4 ✓

extern __shared__ float vq_smem[];

typedef unsigned long long u64;

__device__ __forceinline__ void fma2(u64& d, u64 a, u64 b) {
    asm("fma.rn.f32x2 %0, %1, %2, %0;" : "+l"(d) : "l"(a), "l"(b));
}
__device__ __forceinline__ void unpack2(float& lo, float& hi, u64 v) {
    asm("mov.b64 {%0, %1}, %2;" : "=f"(lo), "=f"(hi) : "l"(v));
}

__global__ __launch_bounds__(NTHREADS, 1)
void vq_kernel(const float* __restrict__ x,
               const float* __restrict__ embed,
               float* __restrict__ out) {
    float* sX   = vq_smem;
    float* sXsq = vq_smem + OFF_XSQ;
    u64*   sPart = reinterpret_cast<u64*>(vq_smem + OFF_PART);
    int*   sBest = reinterpret_cast<int*>(vq_smem + OFF_BESTK);

    const int tid  = threadIdx.x;
    const int lane = tid & 31;
    const int warp = tid >> 5;
    const int base = blockIdx.x * PPC;

    // ---- Stage x -> SMEM [p][c], coalesced gmem reads ----
    #pragma unroll 1
    for (int c = 0; c < C_DIM; c++) {
        for (int p = tid; p < PPC; p += NTHREADS) {
            int n = base + p; if (n > NPTS - 1) n = NPTS - 1;
            const int b = n >> 10, hw = n & 1023;
            sX[p * XSTRIDE + c] = x[(size_t)b * (C_DIM * HW) + (size_t)c * HW + hw];
        }
    }

    // ---- Codebook rows -> registers: this thread owns rows r0, r1 ----
    const int r0 = warp * 64 + 2 * lane;
    const int r1 = r0 + 1;
    u64 cb0[32], cb1[32];
    {
        const ulonglong2* g0 = reinterpret_cast<const ulonglong2*>(embed + r0 * C_DIM);
        const ulonglong2* g1 = reinterpret_cast<const ulonglong2*>(embed + r1 * C_DIM);
        #pragma unroll
        for (int i = 0; i < 16; i++) { ulonglong2 v = g0[i]; cb0[2*i] = v.x; cb0[2*i+1] = v.y; }
        #pragma unroll
        for (int i = 0; i < 16; i++) { ulonglong2 v = g1[i]; cb1[2*i] = v.x; cb1[2*i+1] = v.y; }
    }
    // e_sq per row, sequential channel order (same as R3)
    float esq0 = 0.0f, esq1 = 0.0f;
    #pragma unroll
    for (int i = 0; i < 32; i++) {
        float a, b;
        unpack2(a, b, cb0[i]); esq0 = fmaf(a, a, esq0); esq0 = fmaf(b, b, esq0);
    }
    #pragma unroll
    for (int i = 0; i < 32; i++) {
        float a, b;
        unpack2(a, b, cb1[i]); esq1 = fmaf(a, a, esq1); esq1 = fmaf(b, b, esq1);
    }
    __syncthreads();

    // ---- x_sq per point, sequential channel order (same as R3) ----
    for (int p = tid; p < PPC; p += NTHREADS) {
        const float* xr = sX + p * XSTRIDE;
        float s = 0.0f;
        #pragma unroll
        for (int c = 0; c < C_DIM; c++) s = fmaf(xr[c], xr[c], s);
        sXsq[p] = s;
    }
    __syncthreads();

    // ---- Mainloop: each warp scores its 64 rows for every point ----
    #pragma unroll 1
    for (int pb = 0; pb < PPC; pb += 8) {
        u64 bm[8];
        #pragma unroll
        for (int j = 0; j < 8; j++) {
            int p = pb + j; if (p >= PPC) p = 0;      // tail: compute, don't store
            const ulonglong2* xr = reinterpret_cast<const ulonglong2*>(sX + p * XSTRIDE);
            u64 a0 = 0ULL, a1 = 0ULL, c0 = 0ULL, c1 = 0ULL;
            #pragma unroll
            for (int i = 0; i < 16; i++) {
                ulonglong2 xv = xr[i];                // broadcast LDS.128
                fma2(a0, xv.x, cb0[2*i]);
                fma2(a1, xv.y, cb0[2*i+1]);
                fma2(c0, xv.x, cb1[2*i]);
                fma2(c1, xv.y, cb1[2*i+1]);
            }
            const float xsq = sXsq[p];                // broadcast LDS
            float l0, h0, l1, h1, cross, t, s0, s1;
            unpack2(l0, h0, a0); unpack2(l1, h1, a1);
            cross = (l0 + h0) + (l1 + h1);
            t = xsq + esq0;
            s0 = fmaf(-2.0f, cross, t);
            unpack2(l0, h0, c0); unpack2(l1, h1, c1);
            cross = (l0 + h0) + (l1 + h1);
            t = xsq + esq1;
            s1 = fmaf(-2.0f, cross, t);
            // scores > 0 always (x_sq ~ chi2(64) >> |2*cross|): fp32 bits are
            // order-preserving; k in low bits => u64 min == lex-min, first-index ties
            u64 u0 = ((u64)__float_as_uint(s0) << 32) | (unsigned)r0;
            u64 u1 = ((u64)__float_as_uint(s1) << 32) | (unsigned)r1;
            bm[j] = u0 < u1 ? u0 : u1;
        }
        // warp butterfly lex-min, 8 independent chains interleaved
        #pragma unroll
        for (int off = 16; off >= 1; off >>= 1) {
            #pragma unroll
            for (int j = 0; j < 8; j++) {
                u64 o = __shfl_xor_sync(0xffffffffu, bm[j], off);
                if (o < bm[j]) bm[j] = o;
            }
        }
        if (lane == 0) {
            #pragma unroll
            for (int j = 0; j < 8; j++)
                if (pb + j < PPC) sPart[(size_t)(pb + j) * PART_STR + warp] = bm[j];
        }
    }
    __syncthreads();

    // ---- Combine 8 warp partials (ascending k => first-index preserved) ----
    for (int p = tid; p < PPC; p += NTHREADS) {
        u64 m = sPart[(size_t)p * PART_STR];
        #pragma unroll
        for (int w = 1; w < 8; w++) {
            u64 o = sPart[(size_t)p * PART_STR + w];
            if (o < m) m = o;
        }
        sBest[p] = (int)(unsigned)(m & 0xffffffffULL);
    }
    __syncthreads();

    // ---- Re-stage codebook into SMEM (stride 68 for bank skew) ----
    {
        const float4* eg = reinterpret_cast<const float4*>(embed);
        for (int i = tid; i < K_EMB * (C_DIM / 4); i += NTHREADS) {
            const int row = i >> 4, q = i & 15;
            *reinterpret_cast<float4*>(vq_smem + row * XSTRIDE + q * 4) = eg[i];
        }
    }
    __syncthreads();

    // ---- Gather + coalesced NCHW store ----
    for (int p = tid; p < PPC; p += NTHREADS) {
        const int n = base + p;
        if (n >= NPTS) continue;
        const int bk = sBest[p];
        const int b = n >> 10, hw = n & 1023;
        const float* q = vq_smem + bk * XSTRIDE;
        float* op = out + (size_t)b * (C_DIM * HW) + hw;
        #pragma unroll
        for (int c = 0; c < C_DIM; c++)
            op[(size_t)c * HW] = q[c];
    }
}

extern "C" void kernel_launch(void* const* d_in, const int* in_sizes, int n_in,
                              void* d_out, int out_size) {
    const float* x     = (const float*)d_in[0];   // 64*64*32*32 fp32
    const float* embed = (const float*)d_in[1];   // 512*64 fp32
    float* out = (float*)d_out;

    static bool attr_set = false;
    if (!attr_set) {
        cudaFuncSetAttribute(vq_kernel,
                             cudaFuncAttributeMaxDynamicSharedMemorySize,
                             SMEM_BYTES);
        attr_set = true;
    }
    vq_kernel<<<NCTAS, NTHREADS, SMEM_BYTES>>>(x, embed, out);
}

// round 12
// speedup vs baseline: 1.3339x; 1.3339x over previous
#include <cuda_runtime.h>
#include <cstdint>

// VectorQuantizer R11: R3 structure (codebook in SMEM, 2 points/thread in regs)
// with the k-loop manually unrolled x2 -> 8 independent FFMA2 accumulator
// chains per thread to hide LDS(29)/FMA(4) latency at nw=2/SMSP.
// Per-(point,k) arithmetic is bit-identical to R3 (rel_err 0.0): stride-4
// f32x2 class split, (l0+h0)+(l1+h1), t=x_sq+e_sq, fmaf(-2,cross,t),
// strict < with ascending k (first-index ties).

#define C_DIM     64
#define K_EMB     512
#define HW        1024        // 32*32
#define NPTS      65536       // 64*32*32
#define NTHREADS  256
#define NCTAS     148
#define PPC       443         // ceil(65536/148), <= 2*NTHREADS
#define SMEM_BYTES (K_EMB * C_DIM * 4 + K_EMB * 4)

extern __shared__ float vq_smem[];

typedef unsigned long long u64;

__device__ __forceinline__ void fma2(u64& d, u64 a, u64 b) {
    asm("fma.rn.f32x2 %0, %1, %2, %0;" : "+l"(d) : "l"(a), "l"(b));
}
__device__ __forceinline__ u64 pack2(float lo, float hi) {
    u64 r;
    asm("mov.b64 %0, {%1, %2};" : "=l"(r) : "f"(lo), "f"(hi));
    return r;
}
__device__ __forceinline__ void unpack2(float& lo, float& hi, u64 v) {
    asm("mov.b64 {%0, %1}, %2;" : "=f"(lo), "=f"(hi) : "l"(v));
}

__global__ __launch_bounds__(NTHREADS, 1)
void vq_kernel(const float* __restrict__ x,
               const float* __restrict__ embed,
               float* __restrict__ out) {
    float* sE   = vq_smem;                 // K_EMB * C_DIM floats
    float* sEsq = vq_smem + K_EMB * C_DIM; // K_EMB floats

    const int tid = threadIdx.x;

    // ---- Stage codebook into SMEM (coalesced float4) ----
    {
        const float4* eg = reinterpret_cast<const float4*>(embed);
        float4* sg = reinterpret_cast<float4*>(sE);
        #pragma unroll
        for (int i = 0; i < (K_EMB * C_DIM / 4) / NTHREADS; i++)  // 32 iters
            sg[tid + i * NTHREADS] = eg[tid + i * NTHREADS];
    }
    __syncthreads();

    // ---- e_sq per codebook row (2 rows per thread), sequential fp32 order ----
    #pragma unroll
    for (int r = 0; r < 2; r++) {
        const int krow = tid + r * NTHREADS;
        const float* row = sE + krow * C_DIM;
        float s = 0.0f;
        #pragma unroll
        for (int c = 0; c < C_DIM; c++) s = fmaf(row[c], row[c], s);
        sEsq[krow] = s;
    }
    __syncthreads();

    // ---- Two points per thread ----
    const int base = blockIdx.x * PPC;
    const int n0 = base + tid;                       // always < NPTS
    const bool v1 = (tid < PPC - NTHREADS) && (base + NTHREADS + tid < NPTS);
    const int n1 = v1 ? (base + NTHREADS + tid) : n0; // clamp: compute, skip store

    const int b0 = n0 >> 10, hw0 = n0 & 1023;
    const int b1 = n1 >> 10, hw1 = n1 & 1023;
    const float* xp0 = x + (size_t)b0 * (C_DIM * HW) + hw0;
    const float* xp1 = x + (size_t)b1 * (C_DIM * HW) + hw1;

    u64 xq0[C_DIM / 2], xq1[C_DIM / 2];
    float xsq0 = 0.0f, xsq1 = 0.0f;
    #pragma unroll
    for (int c = 0; c < C_DIM / 2; c++) {
        float a0 = xp0[(size_t)(2 * c)     * HW];
        float a1 = xp0[(size_t)(2 * c + 1) * HW];
        xsq0 = fmaf(a0, a0, xsq0);
        xsq0 = fmaf(a1, a1, xsq0);
        xq0[c] = pack2(a0, a1);
        float d0 = xp1[(size_t)(2 * c)     * HW];
        float d1 = xp1[(size_t)(2 * c + 1) * HW];
        xsq1 = fmaf(d0, d0, xsq1);
        xsq1 = fmaf(d1, d1, xsq1);
        xq1[c] = pack2(d0, d1);
    }

    float best0 = 3.4e38f, best1 = 3.4e38f;
    int bestk0 = 0, bestk1 = 0;
    const ulonglong2* sE2 = reinterpret_cast<const ulonglong2*>(sE);

    // ---- Mainloop: k unrolled x2 -> 8 independent accumulator chains ----
    #pragma unroll 1
    for (int k = 0; k < K_EMB; k += 2) {
        const ulonglong2* rowA = sE2 + k * 16;        // row k
        const ulonglong2* rowB = rowA + 16;           // row k+1
        u64 aA0 = 0, aA1 = 0, cA0 = 0, cA1 = 0;       // (p0,k) (p1,k)
        u64 aB0 = 0, aB1 = 0, cB0 = 0, cB1 = 0;       // (p0,k+1) (p1,k+1)
        #pragma unroll
        for (int i = 0; i < 16; i += 2) {
            ulonglong2 eA0 = rowA[i];
            ulonglong2 eA1 = rowA[i + 1];
            ulonglong2 eB0 = rowB[i];
            ulonglong2 eB1 = rowB[i + 1];
            // row k: identical sequence to R3 (a0/a1 = mod-4 class pairs)
            fma2(aA0, xq0[2 * i],     eA0.x);
            fma2(aA1, xq0[2 * i + 1], eA0.y);
            fma2(cA0, xq1[2 * i],     eA0.x);
            fma2(cA1, xq1[2 * i + 1], eA0.y);
            fma2(aA0, xq0[2 * i + 2], eA1.x);
            fma2(aA1, xq0[2 * i + 3], eA1.y);
            fma2(cA0, xq1[2 * i + 2], eA1.x);
            fma2(cA1, xq1[2 * i + 3], eA1.y);
            // row k+1: same pattern, independent chains
            fma2(aB0, xq0[2 * i],     eB0.x);
            fma2(aB1, xq0[2 * i + 1], eB0.y);
            fma2(cB0, xq1[2 * i],     eB0.x);
            fma2(cB1, xq1[2 * i + 1], eB0.y);
            fma2(aB0, xq0[2 * i + 2], eB1.x);
            fma2(aB1, xq0[2 * i + 3], eB1.y);
            fma2(cB0, xq1[2 * i + 2], eB1.x);
            fma2(cB1, xq1[2 * i + 3], eB1.y);
        }
        const float esqA = sEsq[k];
        const float esqB = sEsq[k + 1];
        float l0, h0, l1, h1, cross, t, score;
        // (p0, k)
        unpack2(l0, h0, aA0); unpack2(l1, h1, aA1);
        cross = (l0 + h0) + (l1 + h1);
        t = xsq0 + esqA;
        score = fmaf(-2.0f, cross, t);
        if (score < best0) { best0 = score; bestk0 = k; }
        // (p1, k)
        unpack2(l0, h0, cA0); unpack2(l1, h1, cA1);
        cross = (l0 + h0) + (l1 + h1);
        t = xsq1 + esqA;
        score = fmaf(-2.0f, cross, t);
        if (score < best1) { best1 = score; bestk1 = k; }
        // (p0, k+1)  -- evaluated after k: ascending order preserved
        unpack2(l0, h0, aB0); unpack2(l1, h1, aB1);
        cross = (l0 + h0) + (l1 + h1);
        t = xsq0 + esqB;
        score = fmaf(-2.0f, cross, t);
        if (score < best0) { best0 = score; bestk0 = k + 1; }
        // (p1, k+1)
        unpack2(l0, h0, cB0); unpack2(l1, h1, cB1);
        cross = (l0 + h0) + (l1 + h1);
        t = xsq1 + esqB;
        score = fmaf(-2.0f, cross, t);
        if (score < best1) { best1 = score; bestk1 = k + 1; }
    }

    // ---- Gather selected rows, strided NCHW stores (coalesced across warp) ----
    {
        const float* q = sE + bestk0 * C_DIM;
        float* op = out + (size_t)b0 * (C_DIM * HW) + hw0;
        #pragma unroll
        for (int c = 0; c < C_DIM; c++)
            op[(size_t)c * HW] = q[c];
    }
    if (v1) {
        const float* q = sE + bestk1 * C_DIM;
        float* op = out + (size_t)b1 * (C_DIM * HW) + hw1;
        #pragma unroll
        for (int c = 0; c < C_DIM; c++)
            op[(size_t)c * HW] = q[c];
    }
}

extern "C" void kernel_launch(void* const* d_in, const int* in_sizes, int n_in,
                              void* d_out, int out_size) {
    const float* x     = (const float*)d_in[0];   // 64*64*32*32 fp32
    const float* embed = (const float*)d_in[1];   // 512*64 fp32
    float* out = (float*)d_out;                   // 64*64*32*32 fp32

    static bool attr_set = false;
    if (!attr_set) {
        cudaFuncSetAttribute(vq_kernel,
                             cudaFuncAttributeMaxDynamicSharedMemorySize,
                             SMEM_BYTES);
        attr_set = true;
    }
    vq_kernel<<<NCTAS, NTHREADS, SMEM_BYTES>>>(x, embed, out);
}

// round 16
// speedup vs baseline: 1.3521x; 1.0137x over previous
#include <cuda_runtime.h>
#include <cuda_bf16.h>
#include <cstdint>
#include <cstring>

// VectorQuantizer R13: classic warp-level bf16 MMA (mma.sync m16n8k16 -- base
// sm_103 ISA, no 'a'-gated tcgen05) + exactness via gap test & exact fallback.
// K1: 3-pass bf16-split GEMM (xh*eh + xh*el + xl*eh), per-point min1/min2 of
//     m_k = esq[k] - 2*cross_k. gap >= 4e-5 -> approx argmin == reference
//     argmin (margin >> split err ~4e-7 + reference rounding ~1.5e-5). Else flag.
// K2: gather+store unflagged points.
// K3: bit-exact R3-chain rescan for flagged (~2%), one warp per point.
// K0: reset flag counter (graph replays).

typedef unsigned long long u64;

#define C_DIM   64
#define K_EMB   512
#define HW      1024
#define NPTS    65536
#define NCTAS   148
#define NTHR    256
#define TILE_M  128
#define TILES   (NPTS / TILE_M)      // 512
#define GAP_THRESH 4e-5f

#define ESTRIDE  144                 // bytes per staged row (72 bf16, 16B-mult)
#define EH_OFF   0                   // 512*144 = 73728
#define EL_OFF   73728               // 73728
#define XH_OFF   147456              // 128*144 = 18432
#define XL_OFF   165888              // 18432
#define ESQ_OFF  184320              // 512 f32 = 2048
#define MV1_OFF  186368              // 128 f32
#define MV2_OFF  186880              // 128 f32
#define MK1_OFF  187392              // 128 int
#define SMEM_BYTES 187904

__device__ int g_best[NPTS];         // bestk | (flag<<31)
__device__ int g_flaglist[NPTS];
__device__ int g_nflag;

// ---------------- helpers ----------------
__device__ __forceinline__ uint32_t smem_u32(const void* p) {
    uint32_t a;
    asm("{ .reg .u64 t; cvta.to.shared.u64 t, %1; cvt.u32.u64 %0, t; }"
        : "=r"(a) : "l"(p));
    return a;
}
__device__ __forceinline__ uint32_t pk(__nv_bfloat16 a, __nv_bfloat16 b) {
    __nv_bfloat162 t = __halves2bfloat162(a, b);
    uint32_t r; memcpy(&r, &t, 4); return r;
}

#define LDSM_X4(r, addr)                                                     \
    asm volatile("ldmatrix.sync.aligned.m8n8.x4.shared.b16 {%0,%1,%2,%3}, [%4];" \
        : "=r"((r)[0]), "=r"((r)[1]), "=r"((r)[2]), "=r"((r)[3]) : "r"(addr))
#define LDSM_X2(r, addr)                                                     \
    asm volatile("ldmatrix.sync.aligned.m8n8.x2.shared.b16 {%0,%1}, [%2];"   \
        : "=r"((r)[0]), "=r"((r)[1]) : "r"(addr))
#define MMA_BF16(d, a, b)                                                    \
    asm volatile("mma.sync.aligned.m16n8k16.row.col.f32.bf16.bf16.f32 "      \
        "{%0,%1,%2,%3}, {%4,%5,%6,%7}, {%8,%9}, {%0,%1,%2,%3};"              \
        : "+f"((d)[0]), "+f"((d)[1]), "+f"((d)[2]), "+f"((d)[3])             \
        : "r"((a)[0]), "r"((a)[1]), "r"((a)[2]), "r"((a)[3]),                \
          "r"((b)[0]), "r"((b)[1]))

// ---------------- Kernel 0: reset flag counter ----------------
__global__ void vq_reset() { if (threadIdx.x == 0) g_nflag = 0; }

// ---------------- Kernel 1: MMA GEMM + candidate selection ----------------
extern __shared__ char k1_smem[];

__global__ __launch_bounds__(NTHR, 1)
void vq_mma_kernel(const float* __restrict__ x,
                   const float* __restrict__ embed) {
    char* sm = k1_smem;
    const uint32_t smb = smem_u32(sm);
    float* sEsq = reinterpret_cast<float*>(sm + ESQ_OFF);
    float* sMV1 = reinterpret_cast<float*>(sm + MV1_OFF);
    float* sMV2 = reinterpret_cast<float*>(sm + MV2_OFF);
    int*   sMK1 = reinterpret_cast<int*>(sm + MK1_OFF);

    const int tid  = threadIdx.x;
    const int warp = tid >> 5;
    const int lane = tid & 31;

    // ---- Stage codebook: eh/el bf16 (16B chunks) ----
    for (int idx = tid; idx < K_EMB * 8; idx += NTHR) {       // 4096
        const int row = idx >> 3, ch = idx & 7;
        const float4* src = reinterpret_cast<const float4*>(embed + row * C_DIM + ch * 8);
        const float4 v0 = src[0], v1 = src[1];
        const float vv[8] = {v0.x, v0.y, v0.z, v0.w, v1.x, v1.y, v1.z, v1.w};
        uint32_t hw_[4], lw_[4];
        #pragma unroll
        for (int j = 0; j < 4; j++) {
            const float a = vv[2 * j], b = vv[2 * j + 1];
            const __nv_bfloat16 ah = __float2bfloat16(a);
            const __nv_bfloat16 bh = __float2bfloat16(b);
            hw_[j] = pk(ah, bh);
            lw_[j] = pk(__float2bfloat16(a - __bfloat162float(ah)),
                        __float2bfloat16(b - __bfloat162float(bh)));
        }
        *reinterpret_cast<uint4*>(sm + EH_OFF + row * ESTRIDE + ch * 16) =
            make_uint4(hw_[0], hw_[1], hw_[2], hw_[3]);
        *reinterpret_cast<uint4*>(sm + EL_OFF + row * ESTRIDE + ch * 16) =
            make_uint4(lw_[0], lw_[1], lw_[2], lw_[3]);
    }
    // esq: sequential fp32 order
    for (int k = tid; k < K_EMB; k += NTHR) {
        const float* row = embed + k * C_DIM;
        float s = 0.0f;
        #pragma unroll
        for (int c = 0; c < C_DIM; c++) s = fmaf(row[c], row[c], s);
        sEsq[k] = s;
    }
    __syncthreads();

    // warp tiling: warp w -> points [mbase, mbase+32), cols [nhalf*256, +256)
    const int mbase = (warp & 3) * 32;
    const int nhalf = warp >> 2;

    // A ldmatrix lane address components (rows 0-15 + k-halves)
    const uint32_t a_lane_off =
        (uint32_t)(lane & 15) * ESTRIDE + (uint32_t)(lane >> 4) * 16;
    // B ldmatrix lane address components
    const uint32_t b_lane_row = (uint32_t)(lane & 7);
    const uint32_t b_lane_kh  = (uint32_t)((lane >> 3) & 1) * 16;

    // ---- Persistent tile loop ----
    for (int t = blockIdx.x; t < TILES; t += NCTAS) {
        const int b   = t >> 3;
        const int hwb = (t & 7) * TILE_M;

        // stage x tile -> xh/xl (c-pairs packed to b32)
        for (int idx = tid; idx < TILE_M * 32; idx += NTHR) {  // 4096
            const int p = idx & 127, cp = idx >> 7;
            const float* xp = x + (size_t)b * (C_DIM * HW) + (size_t)(2 * cp) * HW + hwb + p;
            const float a = xp[0], bb = xp[HW];
            const __nv_bfloat16 ah = __float2bfloat16(a);
            const __nv_bfloat16 bh = __float2bfloat16(bb);
            *reinterpret_cast<uint32_t*>(sm + XH_OFF + p * ESTRIDE + cp * 4) = pk(ah, bh);
            *reinterpret_cast<uint32_t*>(sm + XL_OFF + p * ESTRIDE + cp * 4) =
                pk(__float2bfloat16(a - __bfloat162float(ah)),
                   __float2bfloat16(bb - __bfloat162float(bh)));
        }
        __syncthreads();

        // ---- Load A fragments once per tile: [msub][kstep][4] ----
        uint32_t aH[2][4][4], aL[2][4][4];
        {
            const uint32_t abase = smb + XH_OFF + (uint32_t)mbase * ESTRIDE + a_lane_off;
            #pragma unroll
            for (int ms = 0; ms < 2; ms++)
                #pragma unroll
                for (int ks = 0; ks < 4; ks++) {
                    const uint32_t ad = abase + ms * (16 * ESTRIDE) + ks * 32;
                    LDSM_X4(aH[ms][ks], ad);
                    LDSM_X4(aL[ms][ks], ad + (XL_OFF - XH_OFF));
                }
        }

        // ---- min1/min2 trackers: 4 slots (2 msub x 2 row-halves) ----
        float v1[4], v2[4]; int k1[4];
        #pragma unroll
        for (int s = 0; s < 4; s++) { v1[s] = 3.4e38f; v2[s] = 3.4e38f; k1[s] = 0; }

        const int nbase0 = nhalf * 256;
        #pragma unroll 1
        for (int nsub = 0; nsub < 32; nsub++) {
            const int n0 = nbase0 + nsub * 8;
            uint32_t bh[4][2], bl[4][2];
            const uint32_t bbase = smb + EH_OFF + (uint32_t)(n0 + b_lane_row) * ESTRIDE + b_lane_kh;
            #pragma unroll
            for (int ks = 0; ks < 4; ks++) {
                LDSM_X2(bh[ks], bbase + ks * 32);
                LDSM_X2(bl[ks], bbase + ks * 32 + (EL_OFF - EH_OFF));
            }
            float d0[4] = {0.f, 0.f, 0.f, 0.f};
            float d1[4] = {0.f, 0.f, 0.f, 0.f};
            #pragma unroll
            for (int ks = 0; ks < 4; ks++) {
                MMA_BF16(d0, aH[0][ks], bh[ks]);
                MMA_BF16(d1, aH[1][ks], bh[ks]);
                MMA_BF16(d0, aH[0][ks], bl[ks]);
                MMA_BF16(d1, aH[1][ks], bl[ks]);
                MMA_BF16(d0, aL[0][ks], bh[ks]);
                MMA_BF16(d1, aL[1][ks], bh[ks]);
            }
            // epilogue: m = esq - 2*cross; D frag: d[0],d[1] row t/4 cols c0,c0+1;
            // d[2],d[3] row t/4+8
            const int c0 = n0 + (lane & 3) * 2;
            const float2 e2 = *reinterpret_cast<const float2*>(sEsq + c0);
            #pragma unroll
            for (int ms = 0; ms < 2; ms++) {
                const float* d = (ms == 0) ? d0 : d1;
                const int s0 = ms * 2, s1 = ms * 2 + 1;
                float m;
                m = fmaf(-2.0f, d[0], e2.x);
                if (m < v1[s0]) { v2[s0] = v1[s0]; v1[s0] = m; k1[s0] = c0; }
                else v2[s0] = fminf(v2[s0], m);
                m = fmaf(-2.0f, d[1], e2.y);
                if (m < v1[s0]) { v2[s0] = v1[s0]; v1[s0] = m; k1[s0] = c0 + 1; }
                else v2[s0] = fminf(v2[s0], m);
                m = fmaf(-2.0f, d[2], e2.x);
                if (m < v1[s1]) { v2[s1] = v1[s1]; v1[s1] = m; k1[s1] = c0; }
                else v2[s1] = fminf(v2[s1], m);
                m = fmaf(-2.0f, d[3], e2.y);
                if (m < v1[s1]) { v2[s1] = v1[s1]; v1[s1] = m; k1[s1] = c0 + 1; }
                else v2[s1] = fminf(v2[s1], m);
            }
        }

        // ---- merge across the 4 lanes sharing each row (lex on (v1,k1)) ----
        #pragma unroll
        for (int off = 1; off <= 2; off <<= 1) {
            #pragma unroll
            for (int s = 0; s < 4; s++) {
                const float ov1 = __shfl_xor_sync(0xffffffffu, v1[s], off);
                const float ov2 = __shfl_xor_sync(0xffffffffu, v2[s], off);
                const int   ok1 = __shfl_xor_sync(0xffffffffu, k1[s], off);
                const bool take = (ov1 < v1[s]) || (ov1 == v1[s] && ok1 < k1[s]);
                const float lose = take ? v1[s] : ov1;
                if (take) { v1[s] = ov1; k1[s] = ok1; }
                v2[s] = fminf(fminf(v2[s], ov2), lose);
            }
        }

        // half1 publishes; half0 merges (half0 ks < half1 ks: first-index kept)
        if (nhalf == 1 && (lane & 3) == 0) {
            #pragma unroll
            for (int s = 0; s < 4; s++) {
                const int row = mbase + (s >> 1) * 16 + (s & 1) * 8 + (lane >> 2);
                sMV1[row] = v1[s]; sMV2[row] = v2[s]; sMK1[row] = k1[s];
            }
        }
        __syncthreads();
        if (nhalf == 0 && (lane & 3) == 0) {
            #pragma unroll
            for (int s = 0; s < 4; s++) {
                const int row = mbase + (s >> 1) * 16 + (s & 1) * 8 + (lane >> 2);
                const float bv1 = sMV1[row], bv2 = sMV2[row];
                const int bk = sMK1[row];
                float fv1, fv2; int fk;
                if (bv1 < v1[s]) { fv1 = bv1; fk = bk; fv2 = fminf(v1[s], bv2); }
                else             { fv1 = v1[s]; fk = k1[s]; fv2 = fminf(v2[s], bv1); }
                const int n = t * TILE_M + row;
                const bool flag = (fv2 - fv1) < GAP_THRESH;
                g_best[n] = fk | (flag ? (int)0x80000000 : 0);
                if (flag) {
                    const int ix = atomicAdd(&g_nflag, 1);
                    g_flaglist[ix] = n;
                }
            }
        }
        // next-iteration staging barrier also orders sMV reads before rewrites
    }
}

// ---------------- Kernel 2: gather + store (unflagged) ----------------
__global__ __launch_bounds__(NTHR, 1)
void vq_gather_kernel(const float* __restrict__ embed,
                      float* __restrict__ out) {
    const int n = blockIdx.x * NTHR + threadIdx.x;
    const int v = g_best[n];
    if (v & 0x80000000) return;     // kernel 3 handles flagged
    const float4* row = reinterpret_cast<const float4*>(embed + v * C_DIM);
    float4 r[16];
    #pragma unroll
    for (int i = 0; i < 16; i++) r[i] = row[i];
    const int b = n >> 10, hw = n & 1023;
    float* op = out + (size_t)b * (C_DIM * HW) + hw;
    #pragma unroll
    for (int i = 0; i < 16; i++) {
        op[(size_t)(4 * i + 0) * HW] = r[i].x;
        op[(size_t)(4 * i + 1) * HW] = r[i].y;
        op[(size_t)(4 * i + 2) * HW] = r[i].z;
        op[(size_t)(4 * i + 3) * HW] = r[i].w;
    }
}

// ---------------- Kernel 3: exact rescan for flagged points ----------------
__global__ __launch_bounds__(NTHR, 1)
void vq_exact_kernel(const float* __restrict__ x,
                     const float* __restrict__ embed,
                     float* __restrict__ out) {
    const int gw = (blockIdx.x * NTHR + threadIdx.x) >> 5;
    const int lid = threadIdx.x & 31;
    const int nwarps = (gridDim.x * NTHR) >> 5;
    const int nf = g_nflag;

    for (int i = gw; i < nf; i += nwarps) {
        const int n = g_flaglist[i];
        const int b = n >> 10, hw = n & 1023;
        const float* xp = x + (size_t)b * (C_DIM * HW) + hw;
        float xv[C_DIM];
        float xsq = 0.0f;
        #pragma unroll
        for (int c = 0; c < C_DIM; c++) {
            xv[c] = xp[(size_t)c * HW];      // broadcast (all lanes same n)
            xsq = fmaf(xv[c], xv[c], xsq);
        }
        u64 best = ~0ULL;
        #pragma unroll 1
        for (int j = 0; j < 16; j++) {
            const int k = lid * 16 + j;      // ascending within lane
            const float4* er = reinterpret_cast<const float4*>(embed + k * C_DIM);
            float s0 = 0, s1 = 0, s2 = 0, s3 = 0, esq = 0;
            #pragma unroll
            for (int q = 0; q < 16; q++) {
                const float4 e = er[q];
                s0 = fmaf(xv[4 * q + 0], e.x, s0);
                s1 = fmaf(xv[4 * q + 1], e.y, s1);
                s2 = fmaf(xv[4 * q + 2], e.z, s2);
                s3 = fmaf(xv[4 * q + 3], e.w, s3);
                esq = fmaf(e.x, e.x, esq); esq = fmaf(e.y, e.y, esq);
                esq = fmaf(e.z, e.z, esq); esq = fmaf(e.w, e.w, esq);
            }
            const float cross = (s0 + s1) + (s2 + s3);  // exact R3 chain
            const float t = xsq + esq;
            const float s = fmaf(-2.0f, cross, t);
            const u64 u = ((u64)__float_as_uint(s) << 32) | (unsigned)k;
            if (u < best) best = u;          // scores > 0: bits order-preserving
        }
        #pragma unroll
        for (int off = 16; off >= 1; off >>= 1) {
            const u64 o = __shfl_xor_sync(0xffffffffu, best, off);
            if (o < best) best = o;
        }
        const int bk = (int)(unsigned)(best & 0xffffffffULL);
        float* op = out + (size_t)b * (C_DIM * HW) + hw;
        for (int c = lid; c < C_DIM; c += 32)
            op[(size_t)c * HW] = embed[bk * C_DIM + c];
    }
}

// ---------------- launch ----------------
extern "C" void kernel_launch(void* const* d_in, const int* in_sizes, int n_in,
                              void* d_out, int out_size) {
    const float* x     = (const float*)d_in[0];
    const float* embed = (const float*)d_in[1];
    float* out = (float*)d_out;

    static bool attr_set = false;
    if (!attr_set) {
        cudaFuncSetAttribute(vq_mma_kernel,
                             cudaFuncAttributeMaxDynamicSharedMemorySize,
                             SMEM_BYTES);
        attr_set = true;
    }
    vq_reset<<<1, 32>>>();
    vq_mma_kernel<<<NCTAS, NTHR, SMEM_BYTES>>>(x, embed);
    vq_gather_kernel<<<NPTS / NTHR, NTHR>>>(embed, out);
    vq_exact_kernel<<<64, NTHR>>>(x, embed, out);
}

// round 17
// speedup vs baseline: 1.6793x; 1.2420x over previous
#include <cuda_runtime.h>
#include <cuda_bf16.h>
#include <cstdint>
#include <cstring>

// VectorQuantizer R16: R13 MMA core (validated rel_err 0.0) +
//  1. K3 rewritten: embed staged to SMEM stride-65 (conflict-free scalar LDS,
//     k = j*32+lane), exact R13 score chain preserved byte-for-byte.
//  2. GAP_THRESH 4e-5 -> 2.2e-5 (bound: 2*(split 1.2e-6 + ref-rounding 7.6e-6)
//     = 1.8e-5; ties always flagged -> exactness preserved).
//  3. K2 folded into K1 tile epilogue (smem bestk + L1-resident embed gather,
//     coalesced NCHW stores).

typedef unsigned long long u64;

#define C_DIM   64
#define K_EMB   512
#define HW      1024
#define NPTS    65536
#define NCTAS   148
#define NTHR    256
#define TILE_M  128
#define TILES   (NPTS / TILE_M)      // 512
#define GAP_THRESH 2.2e-5f

#define ESTRIDE  144                 // bytes per staged row (72 bf16, 16B-mult)
#define EH_OFF   0                   // 512*144 = 73728
#define EL_OFF   73728               // 73728
#define XH_OFF   147456              // 128*144 = 18432
#define XL_OFF   165888              // 18432
#define ESQ_OFF  184320              // 512 f32 = 2048
#define MV1_OFF  186368              // 128 f32
#define MV2_OFF  186880              // 128 f32
#define MK1_OFF  187392              // 128 int
#define SBK_OFF  187904              // 128 int
#define SMEM_BYTES 188416

// K3 smem: 512 rows * 65 floats + 512 esq
#define K3_ESTR   65
#define K3_SMEM_FLOATS (K_EMB * K3_ESTR + K_EMB)
#define K3_SMEM_BYTES  (K3_SMEM_FLOATS * 4)   // 135168

__device__ int g_flaglist[NPTS];
__device__ int g_nflag;

// ---------------- helpers ----------------
__device__ __forceinline__ uint32_t smem_u32(const void* p) {
    uint32_t a;
    asm("{ .reg .u64 t; cvta.to.shared.u64 t, %1; cvt.u32.u64 %0, t; }"
        : "=r"(a) : "l"(p));
    return a;
}
__device__ __forceinline__ uint32_t pk(__nv_bfloat16 a, __nv_bfloat16 b) {
    __nv_bfloat162 t = __halves2bfloat162(a, b);
    uint32_t r; memcpy(&r, &t, 4); return r;
}

#define LDSM_X4(r, addr)                                                     \
    asm volatile("ldmatrix.sync.aligned.m8n8.x4.shared.b16 {%0,%1,%2,%3}, [%4];" \
        : "=r"((r)[0]), "=r"((r)[1]), "=r"((r)[2]), "=r"((r)[3]) : "r"(addr))
#define LDSM_X2(r, addr)                                                     \
    asm volatile("ldmatrix.sync.aligned.m8n8.x2.shared.b16 {%0,%1}, [%2];"   \
        : "=r"((r)[0]), "=r"((r)[1]) : "r"(addr))
#define MMA_BF16(d, a, b)                                                    \
    asm volatile("mma.sync.aligned.m16n8k16.row.col.f32.bf16.bf16.f32 "      \
        "{%0,%1,%2,%3}, {%4,%5,%6,%7}, {%8,%9}, {%0,%1,%2,%3};"              \
        : "+f"((d)[0]), "+f"((d)[1]), "+f"((d)[2]), "+f"((d)[3])             \
        : "r"((a)[0]), "r"((a)[1]), "r"((a)[2]), "r"((a)[3]),                \
          "r"((b)[0]), "r"((b)[1]))

// ---------------- Kernel 0: reset flag counter ----------------
__global__ void vq_reset() { if (threadIdx.x == 0) g_nflag = 0; }

// ---------------- Kernel 1: MMA GEMM + selection + gather/store ----------------
__global__ __launch_bounds__(NTHR, 1)
void vq_mma_kernel(const float* __restrict__ x,
                   const float* __restrict__ embed,
                   float* __restrict__ out) {
    extern __shared__ char sm[];
    const uint32_t smb = smem_u32(sm);
    float* sEsq = reinterpret_cast<float*>(sm + ESQ_OFF);
    float* sMV1 = reinterpret_cast<float*>(sm + MV1_OFF);
    float* sMV2 = reinterpret_cast<float*>(sm + MV2_OFF);
    int*   sMK1 = reinterpret_cast<int*>(sm + MK1_OFF);
    int*   sBK  = reinterpret_cast<int*>(sm + SBK_OFF);

    const int tid  = threadIdx.x;
    const int warp = tid >> 5;
    const int lane = tid & 31;

    // ---- Stage codebook: eh/el bf16 (16B chunks) ----
    for (int idx = tid; idx < K_EMB * 8; idx += NTHR) {       // 4096
        const int row = idx >> 3, ch = idx & 7;
        const float4* src = reinterpret_cast<const float4*>(embed + row * C_DIM + ch * 8);
        const float4 v0 = src[0], v1 = src[1];
        const float vv[8] = {v0.x, v0.y, v0.z, v0.w, v1.x, v1.y, v1.z, v1.w};
        uint32_t hw_[4], lw_[4];
        #pragma unroll
        for (int j = 0; j < 4; j++) {
            const float a = vv[2 * j], b = vv[2 * j + 1];
            const __nv_bfloat16 ah = __float2bfloat16(a);
            const __nv_bfloat16 bh = __float2bfloat16(b);
            hw_[j] = pk(ah, bh);
            lw_[j] = pk(__float2bfloat16(a - __bfloat162float(ah)),
                        __float2bfloat16(b - __bfloat162float(bh)));
        }
        *reinterpret_cast<uint4*>(sm + EH_OFF + row * ESTRIDE + ch * 16) =
            make_uint4(hw_[0], hw_[1], hw_[2], hw_[3]);
        *reinterpret_cast<uint4*>(sm + EL_OFF + row * ESTRIDE + ch * 16) =
            make_uint4(lw_[0], lw_[1], lw_[2], lw_[3]);
    }
    // esq: sequential fp32 order
    for (int k = tid; k < K_EMB; k += NTHR) {
        const float* row = embed + k * C_DIM;
        float s = 0.0f;
        #pragma unroll
        for (int c = 0; c < C_DIM; c++) s = fmaf(row[c], row[c], s);
        sEsq[k] = s;
    }
    __syncthreads();

    // warp tiling: warp w -> points [mbase, mbase+32), cols [nhalf*256, +256)
    const int mbase = (warp & 3) * 32;
    const int nhalf = warp >> 2;

    const uint32_t a_lane_off =
        (uint32_t)(lane & 15) * ESTRIDE + (uint32_t)(lane >> 4) * 16;
    const uint32_t b_lane_row = (uint32_t)(lane & 7);
    const uint32_t b_lane_kh  = (uint32_t)((lane >> 3) & 1) * 16;

    // ---- Persistent tile loop ----
    for (int t = blockIdx.x; t < TILES; t += NCTAS) {
        const int b   = t >> 3;
        const int hwb = (t & 7) * TILE_M;

        // stage x tile -> xh/xl (c-pairs packed to b32)
        for (int idx = tid; idx < TILE_M * 32; idx += NTHR) {  // 4096
            const int p = idx & 127, cp = idx >> 7;
            const float* xp = x + (size_t)b * (C_DIM * HW) + (size_t)(2 * cp) * HW + hwb + p;
            const float a = xp[0], bb = xp[HW];
            const __nv_bfloat16 ah = __float2bfloat16(a);
            const __nv_bfloat16 bh = __float2bfloat16(bb);
            *reinterpret_cast<uint32_t*>(sm + XH_OFF + p * ESTRIDE + cp * 4) = pk(ah, bh);
            *reinterpret_cast<uint32_t*>(sm + XL_OFF + p * ESTRIDE + cp * 4) =
                pk(__float2bfloat16(a - __bfloat162float(ah)),
                   __float2bfloat16(bb - __bfloat162float(bh)));
        }
        __syncthreads();

        // ---- Load A fragments once per tile ----
        uint32_t aH[2][4][4], aL[2][4][4];
        {
            const uint32_t abase = smb + XH_OFF + (uint32_t)mbase * ESTRIDE + a_lane_off;
            #pragma unroll
            for (int ms = 0; ms < 2; ms++)
                #pragma unroll
                for (int ks = 0; ks < 4; ks++) {
                    const uint32_t ad = abase + ms * (16 * ESTRIDE) + ks * 32;
                    LDSM_X4(aH[ms][ks], ad);
                    LDSM_X4(aL[ms][ks], ad + (XL_OFF - XH_OFF));
                }
        }

        float v1[4], v2[4]; int k1[4];
        #pragma unroll
        for (int s = 0; s < 4; s++) { v1[s] = 3.4e38f; v2[s] = 3.4e38f; k1[s] = 0; }

        const int nbase0 = nhalf * 256;
        #pragma unroll 1
        for (int nsub = 0; nsub < 32; nsub++) {
            const int n0 = nbase0 + nsub * 8;
            uint32_t bh[4][2], bl[4][2];
            const uint32_t bbase = smb + EH_OFF + (uint32_t)(n0 + b_lane_row) * ESTRIDE + b_lane_kh;
            #pragma unroll
            for (int ks = 0; ks < 4; ks++) {
                LDSM_X2(bh[ks], bbase + ks * 32);
                LDSM_X2(bl[ks], bbase + ks * 32 + (EL_OFF - EH_OFF));
            }
            float d0[4] = {0.f, 0.f, 0.f, 0.f};
            float d1[4] = {0.f, 0.f, 0.f, 0.f};
            #pragma unroll
            for (int ks = 0; ks < 4; ks++) {
                MMA_BF16(d0, aH[0][ks], bh[ks]);
                MMA_BF16(d1, aH[1][ks], bh[ks]);
                MMA_BF16(d0, aH[0][ks], bl[ks]);
                MMA_BF16(d1, aH[1][ks], bl[ks]);
                MMA_BF16(d0, aL[0][ks], bh[ks]);
                MMA_BF16(d1, aL[1][ks], bh[ks]);
            }
            const int c0 = n0 + (lane & 3) * 2;
            const float2 e2 = *reinterpret_cast<const float2*>(sEsq + c0);
            #pragma unroll
            for (int ms = 0; ms < 2; ms++) {
                const float* d = (ms == 0) ? d0 : d1;
                const int s0 = ms * 2, s1 = ms * 2 + 1;
                float m;
                m = fmaf(-2.0f, d[0], e2.x);
                if (m < v1[s0]) { v2[s0] = v1[s0]; v1[s0] = m; k1[s0] = c0; }
                else v2[s0] = fminf(v2[s0], m);
                m = fmaf(-2.0f, d[1], e2.y);
                if (m < v1[s0]) { v2[s0] = v1[s0]; v1[s0] = m; k1[s0] = c0 + 1; }
                else v2[s0] = fminf(v2[s0], m);
                m = fmaf(-2.0f, d[2], e2.x);
                if (m < v1[s1]) { v2[s1] = v1[s1]; v1[s1] = m; k1[s1] = c0; }
                else v2[s1] = fminf(v2[s1], m);
                m = fmaf(-2.0f, d[3], e2.y);
                if (m < v1[s1]) { v2[s1] = v1[s1]; v1[s1] = m; k1[s1] = c0 + 1; }
                else v2[s1] = fminf(v2[s1], m);
            }
        }

        // ---- merge across the 4 lanes sharing each row ----
        #pragma unroll
        for (int off = 1; off <= 2; off <<= 1) {
            #pragma unroll
            for (int s = 0; s < 4; s++) {
                const float ov1 = __shfl_xor_sync(0xffffffffu, v1[s], off);
                const float ov2 = __shfl_xor_sync(0xffffffffu, v2[s], off);
                const int   ok1 = __shfl_xor_sync(0xffffffffu, k1[s], off);
                const bool take = (ov1 < v1[s]) || (ov1 == v1[s] && ok1 < k1[s]);
                const float lose = take ? v1[s] : ov1;
                if (take) { v1[s] = ov1; k1[s] = ok1; }
                v2[s] = fminf(fminf(v2[s], ov2), lose);
            }
        }

        if (nhalf == 1 && (lane & 3) == 0) {
            #pragma unroll
            for (int s = 0; s < 4; s++) {
                const int row = mbase + (s >> 1) * 16 + (s & 1) * 8 + (lane >> 2);
                sMV1[row] = v1[s]; sMV2[row] = v2[s]; sMK1[row] = k1[s];
            }
        }
        __syncthreads();
        if (nhalf == 0 && (lane & 3) == 0) {
            #pragma unroll
            for (int s = 0; s < 4; s++) {
                const int row = mbase + (s >> 1) * 16 + (s & 1) * 8 + (lane >> 2);
                const float bv1 = sMV1[row], bv2 = sMV2[row];
                const int bk = sMK1[row];
                float fv1, fv2; int fk;
                if (bv1 < v1[s]) { fv1 = bv1; fk = bk; fv2 = fminf(v1[s], bv2); }
                else             { fv1 = v1[s]; fk = k1[s]; fv2 = fminf(v2[s], bv1); }
                const bool flag = (fv2 - fv1) < GAP_THRESH;
                sBK[row] = fk | (flag ? (int)0x80000000 : 0);
                if (flag) {
                    const int ix = atomicAdd(&g_nflag, 1);
                    g_flaglist[ix] = t * TILE_M + row;
                }
            }
        }
        __syncthreads();

        // ---- folded gather + coalesced NCHW store (unflagged rows) ----
        {
            const int p = tid & 127, h = tid >> 7;   // h in {0,1}: channels h*32..+31
            const int v = sBK[p];
            const float4* row = reinterpret_cast<const float4*>(
                embed + (v & 511) * C_DIM + h * 32);
            float4 r[8];
            #pragma unroll
            for (int i = 0; i < 8; i++) r[i] = row[i];   // L1-resident gather
            if (!(v & 0x80000000)) {
                float* op = out + (size_t)b * (C_DIM * HW)
                                + (size_t)(h * 32) * HW + hwb + p;
                #pragma unroll
                for (int i = 0; i < 8; i++) {
                    op[(size_t)(4 * i + 0) * HW] = r[i].x;
                    op[(size_t)(4 * i + 1) * HW] = r[i].y;
                    op[(size_t)(4 * i + 2) * HW] = r[i].z;
                    op[(size_t)(4 * i + 3) * HW] = r[i].w;
                }
            }
        }
        // staging __syncthreads at top of next iteration orders sBK reuse
    }
}

// ---------------- Kernel 3: exact rescan (smem-staged, conflict-free) --------
__global__ __launch_bounds__(NTHR, 1)
void vq_exact_kernel(const float* __restrict__ x,
                     const float* __restrict__ embed,
                     float* __restrict__ out) {
    if (g_nflag == 0) return;     // uniform across all threads
    extern __shared__ char sraw[];
    float* sE   = reinterpret_cast<float*>(sraw);     // 512 rows * 65
    float* sEsq = sE + K_EMB * K3_ESTR;

    const int tid = threadIdx.x;
    const int lid = tid & 31;

    // stage embed fp32 (coalesced reads; stride-65 rows)
    for (int idx = tid; idx < K_EMB * C_DIM; idx += NTHR)
        sE[(idx >> 6) * K3_ESTR + (idx & 63)] = embed[idx];
    __syncthreads();
    // exact esq chain (sequential c)
    for (int k = tid; k < K_EMB; k += NTHR) {
        const float* row = sE + k * K3_ESTR;
        float s = 0.0f;
        #pragma unroll
        for (int c = 0; c < C_DIM; c++) s = fmaf(row[c], row[c], s);
        sEsq[k] = s;
    }
    __syncthreads();

    const int gw = (blockIdx.x * NTHR + tid) >> 5;
    const int nwarps = (gridDim.x * NTHR) >> 5;
    const int nf = g_nflag;

    for (int i = gw; i < nf; i += nwarps) {
        const int n = g_flaglist[i];
        const int b = n >> 10, hw = n & 1023;
        const float* xp = x + (size_t)b * (C_DIM * HW) + hw;
        float xv[C_DIM];
        float xsq = 0.0f;
        #pragma unroll
        for (int c = 0; c < C_DIM; c++) {
            xv[c] = xp[(size_t)c * HW];      // broadcast (all lanes same n)
            xsq = fmaf(xv[c], xv[c], xsq);
        }
        u64 best = ~0ULL;
        #pragma unroll 1
        for (int j = 0; j < 16; j++) {
            const int k = j * 32 + lid;      // stride-65 => bank = lane: conflict-free
            const float* er = sE + k * K3_ESTR;
            float s0 = 0, s1 = 0, s2 = 0, s3 = 0;
            #pragma unroll
            for (int q = 0; q < 16; q++) {   // exact R13 chain (mod-4 classes)
                s0 = fmaf(xv[4 * q + 0], er[4 * q + 0], s0);
                s1 = fmaf(xv[4 * q + 1], er[4 * q + 1], s1);
                s2 = fmaf(xv[4 * q + 2], er[4 * q + 2], s2);
                s3 = fmaf(xv[4 * q + 3], er[4 * q + 3], s3);
            }
            const float cross = (s0 + s1) + (s2 + s3);
            const float t = xsq + sEsq[k];
            const float s = fmaf(-2.0f, cross, t);
            const u64 u = ((u64)__float_as_uint(s) << 32) | (unsigned)k;
            if (u < best) best = u;          // scores > 0: bits order-preserving
        }
        #pragma unroll
        for (int off = 16; off >= 1; off >>= 1) {
            const u64 o = __shfl_xor_sync(0xffffffffu, best, off);
            if (o < best) best = o;
        }
        const int bk = (int)(unsigned)(best & 0xffffffffULL);
        float* op = out + (size_t)b * (C_DIM * HW) + hw;
        for (int c = lid; c < C_DIM; c += 32)
            op[(size_t)c * HW] = sE[bk * K3_ESTR + c];
    }
}

// ---------------- launch ----------------
extern "C" void kernel_launch(void* const* d_in, const int* in_sizes, int n_in,
                              void* d_out, int out_size) {
    const float* x     = (const float*)d_in[0];
    const float* embed = (const float*)d_in[1];
    float* out = (float*)d_out;

    static bool attr_set = false;
    if (!attr_set) {
        cudaFuncSetAttribute(vq_mma_kernel,
                             cudaFuncAttributeMaxDynamicSharedMemorySize,
                             SMEM_BYTES);
        cudaFuncSetAttribute(vq_exact_kernel,
                             cudaFuncAttributeMaxDynamicSharedMemorySize,
                             K3_SMEM_BYTES);
        attr_set = true;
    }
    vq_reset<<<1, 32>>>();
    vq_mma_kernel<<<NCTAS, NTHR, SMEM_BYTES>>>(x, embed, out);
    vq_exact_kernel<<<NCTAS, NTHR, K3_SMEM_BYTES>>>(x, embed, out);
}